// round 10
// baseline (speedup 1.0000x reference)
#include <cuda_runtime.h>
#include <cstdint>

#define T_LEN   16384
#define T_MASK  16383
#define L_HALF  50
#define NMN     449
#define NK      11
#define NOUT    16284      // T - 2*L
#define TILE_T  512
#define THREADS 256
#define CHUNK   64
#define HALF0   225        // q-pairs [0,225) -> half 0, [225,449) -> half 1

typedef unsigned long long u64;

// -------- compile-time pair tables --------
// Reference enumerates (m outer, n inner). We iterate in n-outer order for
// E(t-n) register reuse; src[] maps our order q -> reference index p so the
// pack kernel permutes coefficients into q-order.
struct Tabs { short m[NMN]; short n[NMN]; short src[NMN]; };
constexpr Tabs make_tabs() {
    Tabs t{};
    short om[NMN] = {}, on[NMN] = {};
    int c = 0;
    for (int m = -25; m <= 25; ++m)
        for (int n = -25; n <= 25; ++n) {
            int pr = m * n; if (pr < 0) pr = -pr;
            if (pr <= 25) { om[c] = (short)m; on[c] = (short)n; ++c; }
        }
    int q = 0;
    for (int n = -25; n <= 25; ++n)
        for (int p = 0; p < NMN; ++p)
            if (on[p] == n) { t.m[q] = om[p]; t.n[q] = (short)n; t.src[q] = (short)p; ++q; }
    return t;
}
__constant__ Tabs c_tab = make_tabs();

// -------- device scratch --------
// per q-pair layout: [0]=cp, [1..11]=C1_j, [12..22]=C2_j  (dual FFMA2 layout)
__device__ float4 g_coef[2][NMN][23];
__device__ float2 g_part[2][2 * NOUT];

// -------- packed f32x2 helpers --------
static __device__ __forceinline__ u64 f2fma(u64 a, u64 b, u64 c) {
    u64 d; asm("fma.rn.f32x2 %0, %1, %2, %3;" : "=l"(d) : "l"(a), "l"(b), "l"(c)); return d;
}
static __device__ __forceinline__ u64 f2mul(u64 a, u64 b) {
    u64 d; asm("mul.rn.f32x2 %0, %1, %2;" : "=l"(d) : "l"(a), "l"(b)); return d;
}
static __device__ __forceinline__ u64 pk2(float lo, float hi) {
    u64 d; asm("mov.b64 %0, {%1, %2};" : "=l"(d) : "f"(lo), "f"(hi)); return d;
}
static __device__ __forceinline__ float2 up2(u64 v) {
    float2 r; asm("mov.b64 {%0, %1}, %2;" : "=f"(r.x), "=f"(r.y) : "l"(v)); return r;
}
static __device__ __forceinline__ u64 ng2(u64 v) { return v ^ 0x8000000080000000ULL; }

// -------- pack coefficients (batch select, power factors, q-order permute) ----
__global__ void sopbc_pack(const float* __restrict__ ti,
                           const float* __restrict__ pbcr, const float* __restrict__ pbci,
                           const float* __restrict__ c1r,  const float* __restrict__ c1i,
                           const float* __restrict__ c2r,  const float* __restrict__ c2i) {
    int idx = blockIdx.x * blockDim.x + threadIdx.x;
    if (idx >= 2 * NMN) return;
    int b = idx / NMN;
    int q = idx % NMN;
    int src = c_tab.src[q];

    int xi = (int)(ti[b * 4 + 2] / 2.0e9f);
    int ind = 0;
    if (xi == 20) ind = 0;
    else if (xi == 40) ind = 1;
    else if (xi == 80) ind = 2;
    else if (xi == 160) ind = 3;

    float P  = exp10f(ti[b * 4 + 0] * 0.1f);
    float sp = sqrtf(P);
    float f3 = sp * sp * sp;
    float f5 = f3 * sp * sp;

    float4* dst = &g_coef[b][q][0];
    float cpr = f3 * pbcr[ind * NMN + src];
    float cpi = f3 * pbci[ind * NMN + src];
    dst[0] = make_float4(cpr, cpi, -cpi, cpr);

    int cb = ind * (NMN * NK) + src * NK;
#pragma unroll
    for (int j = 0; j < NK; ++j) {
        float u1 = f5 * c1r[cb + j], w1 = f5 * c1i[cb + j];
        float u2 = f5 * c2r[cb + j], w2 = f5 * c2i[cb + j];
        dst[1 + j]  = make_float4(u1, w1, -w1, u1);   // A * C1
        dst[12 + j] = make_float4(u2, w2, w2, -u2);   // conj(A) * C2
    }
}

// -------- main kernel: ILP4 --------
// grid = (32 t-tiles of 512, 2 batches, 2 pair-halves); 256 threads.
// slot = tid&127 covers t = win0 + slot + {0,128,256,384}.
// warps 0-3 (g=0): A, cp, G1 (A*C1);  warps 4-7 (g=1): A, G2 (conj(A)*C2).
__global__ __launch_bounds__(THREADS, 1)
void sopbc_main(const float* __restrict__ Er, const float* __restrict__ Ei) {
    __shared__ float2 sE[612];
    __shared__ float4 s_cf[CHUNK * 23];
    __shared__ float2 s_red[4][128];

    const int tid  = threadIdx.x;
    const int slot = tid & 127;
    const int g    = tid >> 7;
    const int b    = blockIdx.y;
    const int h    = blockIdx.z;
    const int base = b * T_LEN;
    const int win0 = blockIdx.x * TILE_T;

    for (int i = tid; i < 612; i += THREADS) {
        int t = (win0 + i) & T_MASK;
        sE[i] = make_float2(Er[base + t], Ei[base + t]);
    }

    const int PSTART = h ? HALF0 : 0;
    const int PEND   = h ? NMN   : HALF0;

    u64 X[4][NK];
    u64 A0[4];
#pragma unroll
    for (int t = 0; t < 4; ++t) {
        A0[t] = 0ull;
#pragma unroll
        for (int j = 0; j < NK; ++j) X[t][j] = 0ull;
    }

    const int i1 = slot + L_HALF;

    int prevn = 12345;
    u64 ar12 = 0, ai12 = 0, ar34 = 0, ai34 = 0;

    const float4* gsrc = &g_coef[b][0][0];

    for (int p0 = PSTART; p0 < PEND; p0 += CHUNK) {
        const int np = (PEND - p0 < CHUNK) ? (PEND - p0) : CHUNK;
        __syncthreads();
        {
            const float4* src = gsrc + p0 * 23;
            const int cnt = np * 23;
            for (int i = tid; i < cnt; i += THREADS) s_cf[i] = src[i];
        }
        __syncthreads();

        for (int p = 0; p < np; ++p) {
            const int m = c_tab.m[p0 + p], n = c_tab.n[p0 + p];
            if (n != prevn) {
                prevn = n;
                float2 a1 = sE[i1 - n],       a2 = sE[i1 + 128 - n];
                float2 a3 = sE[i1 + 256 - n], a4 = sE[i1 + 384 - n];
                ar12 = pk2(a1.x, a2.x); ai12 = pk2(a1.y, a2.y);
                ar34 = pk2(a3.x, a4.x); ai34 = pk2(a3.y, a4.y);
            }
            const int im = i1 - m, imn = i1 - m - n;

            // t-pair (1,2)
            u64 R1, I1, R2, I2, R3, I3, R4, I4;
            {
                float2 b1 = sE[imn],       b2 = sE[imn + 128];
                float2 c1 = sE[im],        c2 = sE[im + 128];
                u64 br = pk2(b1.x, b2.x), bi = pk2(b1.y, b2.y);
                u64 cr = pk2(c1.x, c2.x), ci = pk2(c1.y, c2.y);
                u64 ur = f2fma(ai12, bi, f2mul(ar12, br));
                u64 ui = f2fma(ai12, br, f2mul(ng2(ar12), bi));
                u64 Ar = f2fma(ng2(ui), ci, f2mul(ur, cr));
                u64 Ai = f2fma(ur, ci, f2mul(ui, cr));
                float2 arp = up2(Ar), aip = up2(Ai);
                R1 = pk2(arp.x, arp.x); I1 = pk2(aip.x, aip.x);
                R2 = pk2(arp.y, arp.y); I2 = pk2(aip.y, aip.y);
            }
            // t-pair (3,4)
            {
                float2 b3 = sE[imn + 256], b4 = sE[imn + 384];
                float2 c3 = sE[im + 256],  c4 = sE[im + 384];
                u64 br = pk2(b3.x, b4.x), bi = pk2(b3.y, b4.y);
                u64 cr = pk2(c3.x, c4.x), ci = pk2(c3.y, c4.y);
                u64 ur = f2fma(ai34, bi, f2mul(ar34, br));
                u64 ui = f2fma(ai34, br, f2mul(ng2(ar34), bi));
                u64 Ar = f2fma(ng2(ui), ci, f2mul(ur, cr));
                u64 Ai = f2fma(ur, ci, f2mul(ui, cr));
                float2 arp = up2(Ar), aip = up2(Ai);
                R3 = pk2(arp.x, arp.x); I3 = pk2(aip.x, aip.x);
                R4 = pk2(arp.y, arp.y); I4 = pk2(aip.y, aip.y);
            }

            const ulonglong2* cf = reinterpret_cast<const ulonglong2*>(s_cf + p * 23);
            if (g == 0) {
                ulonglong2 c0 = cf[0];
                A0[0] = f2fma(I1, c0.y, f2fma(R1, c0.x, A0[0]));
                A0[1] = f2fma(I2, c0.y, f2fma(R2, c0.x, A0[1]));
                A0[2] = f2fma(I3, c0.y, f2fma(R3, c0.x, A0[2]));
                A0[3] = f2fma(I4, c0.y, f2fma(R4, c0.x, A0[3]));
#pragma unroll
                for (int j = 0; j < NK; ++j) {
                    ulonglong2 c = cf[1 + j];
                    X[0][j] = f2fma(I1, c.y, f2fma(R1, c.x, X[0][j]));
                    X[1][j] = f2fma(I2, c.y, f2fma(R2, c.x, X[1][j]));
                    X[2][j] = f2fma(I3, c.y, f2fma(R3, c.x, X[2][j]));
                    X[3][j] = f2fma(I4, c.y, f2fma(R4, c.x, X[3][j]));
                }
            } else {
#pragma unroll
                for (int j = 0; j < NK; ++j) {
                    ulonglong2 c = cf[12 + j];
                    X[0][j] = f2fma(I1, c.y, f2fma(R1, c.x, X[0][j]));
                    X[1][j] = f2fma(I2, c.y, f2fma(R2, c.x, X[1][j]));
                    X[2][j] = f2fma(I3, c.y, f2fma(R3, c.x, X[2][j]));
                    X[3][j] = f2fma(I4, c.y, f2fma(R4, c.x, X[3][j]));
                }
            }
        }
    }

    // ---- epilogue ----
    if (g == 1) {
        // partial: sum_j Q * G2  per t
#pragma unroll
        for (int t = 0; t < 4; ++t) {
            const int it = i1 + t * 128;
            float pr = 0.f, pi = 0.f;
#pragma unroll
            for (int j = 0; j < NK; ++j) {
                float2 e  = sE[it + 5 - j];
                float Qr  = e.x * e.x - e.y * e.y;
                float Qi  = 2.f * e.x * e.y;
                float2 g2 = up2(X[t][j]);
                pr += Qr * g2.x - Qi * g2.y;
                pi += Qr * g2.y + Qi * g2.x;
            }
            s_red[t][slot] = make_float2(pr, pi);
        }
    }
    __syncthreads();
    if (g == 0) {
        float2* dst = &g_part[h][b * NOUT];
#pragma unroll
        for (int t = 0; t < 4; ++t) {
            const int it = i1 + t * 128;
            const int to = win0 + slot + t * 128;
            if (t < 3 || to < NOUT) {
                float2 r  = s_red[t][slot];
                float2 cp = up2(A0[t]);
                float er = cp.x + r.x, eim = cp.y + r.y;
                if (h == 0) { float2 e0 = sE[it]; er += e0.x; eim += e0.y; }
#pragma unroll
                for (int j = 0; j < NK; ++j) {
                    float2 e  = sE[it + 5 - j];
                    float Iv  = e.x * e.x + e.y * e.y;
                    float2 g1 = up2(X[t][j]);
                    er  += Iv * g1.x;
                    eim += Iv * g1.y;
                }
                dst[to] = make_float2(er, eim);
            }
        }
    }
}

// -------- combine: out = part[0] + part[1] --------
__global__ void sopbc_combine(float* __restrict__ out) {
    int i = blockIdx.x * blockDim.x + threadIdx.x;
    if (i >= 2 * NOUT) return;
    float2 a = g_part[0][i];
    float2 c = g_part[1][i];
    reinterpret_cast<float2*>(out)[i] = make_float2(a.x + c.x, a.y + c.y);
}

extern "C" void kernel_launch(void* const* d_in, const int* in_sizes, int n_in,
                              void* d_out, int out_size) {
    const float* Er   = (const float*)d_in[0];
    const float* Ei   = (const float*)d_in[1];
    const float* ti   = (const float*)d_in[2];
    const float* pbcr = (const float*)d_in[3];
    const float* pbci = (const float*)d_in[4];
    const float* c1r  = (const float*)d_in[5];
    const float* c1i  = (const float*)d_in[6];
    const float* c2r  = (const float*)d_in[7];
    const float* c2i  = (const float*)d_in[8];
    float* out = (float*)d_out;

    sopbc_pack<<<(2 * NMN + 127) / 128, 128>>>(ti, pbcr, pbci, c1r, c1i, c2r, c2i);

    dim3 grid(32, 2, 2);
    sopbc_main<<<grid, THREADS>>>(Er, Ei);

    sopbc_combine<<<(2 * NOUT + 255) / 256, 256>>>(out);
}